// round 3
// baseline (speedup 1.0000x reference)
#include <cuda_runtime.h>

#define N_FRAMES 16384
#define NUM_BIN  257
#define NUM_CH   8
#define TOTAL    (N_FRAMES * NUM_BIN)
// plane stride within one tensor slot: NUM_BIN*NUM_CH floats
#define PLANE    (NUM_BIN * NUM_CH)   // 2056

__global__ __launch_bounds__(256) void beamform_kernel(
    const float* __restrict__ x,    // [16384, 2, 257, 8]
    const float* __restrict__ W,    // [24, 2, 257, 8]
    const int* __restrict__ beam,   // [16384] (int32 payload)
    float* __restrict__ out)        // [16384, 2, 257, 1]
{
    // 2 threads per (frame, bin): each handles 4 of the 8 channels.
    unsigned g = blockIdx.x * 256u + threadIdx.x;   // < 2*TOTAL exactly
    unsigned e    = g >> 1;        // element index (t, bin)
    unsigned half = g & 1u;        // which 4-channel half
    unsigned t    = e / (unsigned)NUM_BIN;
    unsigned bin  = e - t * (unsigned)NUM_BIN;
    int b = __ldg(beam + t);

    size_t x_base = ((size_t)t * 2 * PLANE) + (size_t)bin * NUM_CH + half * 4;
    size_t w_base = ((size_t)b * 2 * PLANE) + (size_t)bin * NUM_CH + half * 4;

    float4 xr = __ldg((const float4*)(x + x_base));
    float4 xi = __ldg((const float4*)(x + x_base + PLANE));
    float4 wr = __ldg((const float4*)(W + w_base));
    float4 wi = __ldg((const float4*)(W + w_base + PLANE));

    // partial sums over this thread's 4 channels
    float pr = xr.x * wr.x + xr.y * wr.y + xr.z * wr.z + xr.w * wr.w
             + xi.x * wi.x + xi.y * wi.y + xi.z * wi.z + xi.w * wi.w;
    float pi = xi.x * wr.x + xi.y * wr.y + xi.z * wr.z + xi.w * wr.w
             - (xr.x * wi.x + xr.y * wi.y + xr.z * wi.z + xr.w * wi.w);

    // combine with partner lane (other 4 channels)
    pr += __shfl_xor_sync(0xffffffffu, pr, 1);
    pi += __shfl_xor_sync(0xffffffffu, pi, 1);

    // even lane writes out_r, odd lane writes out_i
    size_t o = (size_t)t * (2 * NUM_BIN) + bin + half * NUM_BIN;
    out[o] = half ? pi : pr;
}

extern "C" void kernel_launch(void* const* d_in, const int* in_sizes, int n_in,
                              void* d_out, int out_size) {
    const float* x    = (const float*)d_in[0];
    const float* W    = (const float*)d_in[1];
    const int*   beam = (const int*)d_in[2];
    float*       out  = (float*)d_out;

    unsigned total_threads = 2u * TOTAL;            // 8,421,376
    unsigned threads = 256;
    unsigned blocks = (total_threads + threads - 1) / threads;  // 32896, exact
    beamform_kernel<<<blocks, threads>>>(x, W, beam, out);
}

// round 4
// speedup vs baseline: 1.1055x; 1.1055x over previous
#include <cuda_runtime.h>

#define N_FRAMES 16384
#define HALF_F   (N_FRAMES / 2)       // 8192
#define NUM_BIN  257
#define NUM_CH   8
#define TOTAL    (N_FRAMES * NUM_BIN)
#define PLANE    (NUM_BIN * NUM_CH)   // 2056 floats per (frame, re/im) plane

__device__ __forceinline__ float4 ldcs4(const float* p) {
    return __ldcs((const float4*)p);
}

__global__ __launch_bounds__(256) void beamform_kernel(
    const float* __restrict__ x,    // [16384, 2, 257, 8]
    const float* __restrict__ W,    // [24, 2, 257, 8]
    const int* __restrict__ beam,   // [16384] (int32 payload)
    float* __restrict__ out)        // [16384, 2, 257, 1]
{
    // Each thread: half a bin (4 ch) for frame t AND frame t+8192.
    unsigned g    = blockIdx.x * 256u + threadIdx.x;  // < TOTAL exactly
    unsigned e    = g >> 1;                           // (t, bin) with t < 8192
    unsigned half = g & 1u;
    unsigned t    = e / (unsigned)NUM_BIN;
    unsigned bin  = e - t * (unsigned)NUM_BIN;

    size_t x0 = ((size_t)t * 2 * PLANE) + (size_t)bin * NUM_CH + half * 4;
    size_t x1 = x0 + (size_t)HALF_F * 2 * PLANE;

    // 8 independent streaming loads — front-batched, no dependence on beam gather
    float4 xr0 = ldcs4(x + x0);
    float4 xi0 = ldcs4(x + x0 + PLANE);
    float4 xr1 = ldcs4(x + x1);
    float4 xi1 = ldcs4(x + x1 + PLANE);

    int b0 = __ldg(beam + t);
    int b1 = __ldg(beam + t + HALF_F);

    size_t w0 = ((size_t)b0 * 2 * PLANE) + (size_t)bin * NUM_CH + half * 4;
    size_t w1 = ((size_t)b1 * 2 * PLANE) + (size_t)bin * NUM_CH + half * 4;

    float4 wr0 = __ldg((const float4*)(W + w0));
    float4 wi0 = __ldg((const float4*)(W + w0 + PLANE));
    float4 wr1 = __ldg((const float4*)(W + w1));
    float4 wi1 = __ldg((const float4*)(W + w1 + PLANE));

    float pr0 = xr0.x * wr0.x + xr0.y * wr0.y + xr0.z * wr0.z + xr0.w * wr0.w
              + xi0.x * wi0.x + xi0.y * wi0.y + xi0.z * wi0.z + xi0.w * wi0.w;
    float pi0 = xi0.x * wr0.x + xi0.y * wr0.y + xi0.z * wr0.z + xi0.w * wr0.w
              - (xr0.x * wi0.x + xr0.y * wi0.y + xr0.z * wi0.z + xr0.w * wi0.w);
    float pr1 = xr1.x * wr1.x + xr1.y * wr1.y + xr1.z * wr1.z + xr1.w * wr1.w
              + xi1.x * wi1.x + xi1.y * wi1.y + xi1.z * wi1.z + xi1.w * wi1.w;
    float pi1 = xi1.x * wr1.x + xi1.y * wr1.y + xi1.z * wr1.z + xi1.w * wr1.w
              - (xr1.x * wi1.x + xr1.y * wi1.y + xr1.z * wi1.z + xr1.w * wi1.w);

    // combine with partner lane (other 4 channels)
    pr0 += __shfl_xor_sync(0xffffffffu, pr0, 1);
    pi0 += __shfl_xor_sync(0xffffffffu, pi0, 1);
    pr1 += __shfl_xor_sync(0xffffffffu, pr1, 1);
    pi1 += __shfl_xor_sync(0xffffffffu, pi1, 1);

    // even lane -> out_r, odd lane -> out_i (dense within each region)
    size_t o0 = (size_t)t * (2 * NUM_BIN) + bin + half * NUM_BIN;
    size_t o1 = o0 + (size_t)HALF_F * (2 * NUM_BIN);
    __stcs(out + o0, half ? pi0 : pr0);
    __stcs(out + o1, half ? pi1 : pr1);
}

extern "C" void kernel_launch(void* const* d_in, const int* in_sizes, int n_in,
                              void* d_out, int out_size) {
    const float* x    = (const float*)d_in[0];
    const float* W    = (const float*)d_in[1];
    const int*   beam = (const int*)d_in[2];
    float*       out  = (float*)d_out;

    unsigned total_threads = (unsigned)TOTAL;       // 4,210,688 = 16448 * 256
    unsigned threads = 256;
    unsigned blocks = (total_threads + threads - 1) / threads;
    beamform_kernel<<<blocks, threads>>>(x, W, beam, out);
}